// round 5
// baseline (speedup 1.0000x reference)
#include <cuda_runtime.h>
#include <cuda_fp16.h>
#include <cstdint>

// ============================================================================
// ScaledDotProductAttention  B=4 H=16 S=2048 D=128, causal, fp32 in/out
// FlashAttention-2, mma.sync.m16n8k16 HMMA.
// R5 changes vs R4 (428.6us, rel_err 2.8e-4):
//   * 64-query CTAs, 128 threads -> 2 CTAs/SM: cross-CTA overlap hides the
//     softmax phase + sync bubbles (R4 tensor pipe only 56%).
//   * PV is single-pass (P-hi only); QK keeps Q split hi/lo (2-pass).
//     Calibrated error model: +~2e-4 in quadrature -> ~3.5e-4 total.
//   * softmax in log2 domain (Q pre-scaled by scale*log2e, ex2.approx).
// ============================================================================

static constexpr int SEQ = 2048;
static constexpr int DH  = 128;
static constexpr float SCALE_LOG2E = 0.08838834764831845f * 1.4426950408889634f;

static constexpr int LDH = 136;   // padded SMEM stride in halfs

// SMEM layout (half units): Q split (64 rows) + 2-stage K + 2-stage V
enum : uint32_t {
    QHI_OFF = 0,
    QLO_OFF = QHI_OFF + 64 * LDH,
    KHI_OFF = QLO_OFF + 64 * LDH,      // 2 stages x 64 rows
    VHI_OFF = KHI_OFF + 2 * 64 * LDH,  // 2 stages x 64 rows
    SMEM_HALVES = VHI_OFF + 2 * 64 * LDH
};
static constexpr uint32_t SMEM_BYTES = SMEM_HALVES * 2;   // 104448

// ---------------------------------------------------------------------------
__device__ __forceinline__ uint32_t cvta_s(const void* p) {
    uint32_t a;
    asm("{ .reg .u64 t; cvta.to.shared.u64 t, %1; cvt.u32.u64 %0, t; }"
        : "=r"(a) : "l"(p));
    return a;
}

__device__ __forceinline__ float ex2f(float x) {
    float r;
    asm("ex2.approx.f32 %0, %1;" : "=f"(r) : "f"(x));
    return r;
}

__device__ __forceinline__ void ldsm4(uint32_t r[4], uint32_t addr) {
    asm volatile("ldmatrix.sync.aligned.m8n8.x4.shared.b16 {%0,%1,%2,%3}, [%4];"
                 : "=r"(r[0]), "=r"(r[1]), "=r"(r[2]), "=r"(r[3]) : "r"(addr));
}

__device__ __forceinline__ void ldsm4t(uint32_t r[4], uint32_t addr) {
    asm volatile("ldmatrix.sync.aligned.m8n8.x4.trans.shared.b16 {%0,%1,%2,%3}, [%4];"
                 : "=r"(r[0]), "=r"(r[1]), "=r"(r[2]), "=r"(r[3]) : "r"(addr));
}

__device__ __forceinline__ void mma16816(float d[4], const uint32_t a[4],
                                         const uint32_t b[2]) {
    asm volatile(
        "mma.sync.aligned.m16n8k16.row.col.f32.f16.f16.f32 "
        "{%0,%1,%2,%3}, {%4,%5,%6,%7}, {%8,%9}, {%0,%1,%2,%3};"
        : "+f"(d[0]), "+f"(d[1]), "+f"(d[2]), "+f"(d[3])
        : "r"(a[0]), "r"(a[1]), "r"(a[2]), "r"(a[3]), "r"(b[0]), "r"(b[1]));
}

__device__ __forceinline__ uint32_t packh2(__half a, __half b) {
    return (uint32_t)__half_as_ushort(a) | ((uint32_t)__half_as_ushort(b) << 16);
}

// ---------------------------------------------------------------------------
__global__ void __launch_bounds__(128, 2)
fa2_hmma_kernel(const float* __restrict__ Qg, const float* __restrict__ Kg,
                const float* __restrict__ Vg, float* __restrict__ Og)
{
    extern __shared__ __half sm[];
    const uint32_t sb = cvta_s(sm);
    const int tid  = threadIdx.x;
    const int w    = tid >> 5;                    // 0..3
    const int lane = tid & 31;
    const int g    = lane >> 2;                   // row group 0..7
    const int c    = lane & 3;                    // col pair 0..3
    const int bh   = blockIdx.x;
    const int qt   = 31 - (int)blockIdx.y;        // heavy q-tiles first
    const size_t base = (size_t)bh * SEQ * DH;
    const int qr0  = qt * 64;

    // ldmatrix per-lane address components
    const int a_row  = 16 * w + (lane & 7) + ((lane >> 3) & 1) * 8;
    const int a_col8 = (lane >> 4) * 8;
    const int bk_rowi = (lane & 7) + (lane >> 4) * 8;
    const int bk_col8 = ((lane >> 3) & 1) * 8;
    const int bv_rowi = (lane & 7) + ((lane >> 3) & 1) * 8;
    const int bv_col8 = (lane >> 4) * 8;

    // ---- prologue: Q tile (64 rows) -> split fp16 SMEM (scale*log2e) -------
    #pragma unroll
    for (int i = 0; i < 16; i++) {
        int idx = tid + i * 128;                  // 0..2047
        int row = idx >> 5, c4 = idx & 31;
        float4 v = *(const float4*)(Qg + base + (size_t)(qr0 + row) * DH + 4 * c4);
        v.x *= SCALE_LOG2E; v.y *= SCALE_LOG2E;
        v.z *= SCALE_LOG2E; v.w *= SCALE_LOG2E;
        __half hx = __float2half_rn(v.x), hy = __float2half_rn(v.y);
        __half hz = __float2half_rn(v.z), hw = __float2half_rn(v.w);
        uint32_t p = row * LDH + 4 * c4;
        *(uint32_t*)&sm[QHI_OFF + p]     = packh2(hx, hy);
        *(uint32_t*)&sm[QHI_OFF + p + 2] = packh2(hz, hw);
        *(uint32_t*)&sm[QLO_OFF + p] =
            packh2(__float2half_rn(v.x - __half2float(hx)),
                   __float2half_rn(v.y - __half2float(hy)));
        *(uint32_t*)&sm[QLO_OFF + p + 2] =
            packh2(__float2half_rn(v.z - __half2float(hz)),
                   __float2half_rn(v.w - __half2float(hw)));
    }

    const int nkt = qt + 1;                       // 64-key tiles incl diagonal

    // ---- preload K/V tile 0 into stage 0 -----------------------------------
    #pragma unroll
    for (int i = 0; i < 16; i++) {
        int idx = tid + i * 128;
        int row = idx >> 5, c4 = idx & 31;
        size_t goff = base + (size_t)row * DH + 4 * c4;
        float4 kv = *(const float4*)(Kg + goff);
        float4 vv = *(const float4*)(Vg + goff);
        uint32_t p = row * LDH + 4 * c4;
        *(uint32_t*)&sm[KHI_OFF + p]     = packh2(__float2half_rn(kv.x), __float2half_rn(kv.y));
        *(uint32_t*)&sm[KHI_OFF + p + 2] = packh2(__float2half_rn(kv.z), __float2half_rn(kv.w));
        *(uint32_t*)&sm[VHI_OFF + p]     = packh2(__float2half_rn(vv.x), __float2half_rn(vv.y));
        *(uint32_t*)&sm[VHI_OFF + p + 2] = packh2(__float2half_rn(vv.z), __float2half_rn(vv.w));
    }

    float O_[16][4];
    #pragma unroll
    for (int n = 0; n < 16; n++)
        #pragma unroll
        for (int e = 0; e < 4; e++) O_[n][e] = 0.0f;
    float mA = -1e30f, mB = -1e30f, lA = 0.0f, lB = 0.0f;

    __syncthreads();

    for (int j = 0; j < nkt; j++) {
        const uint32_t kbuf = KHI_OFF + (uint32_t)(j & 1) * 64 * LDH;
        const uint32_t vbuf = VHI_OFF + (uint32_t)(j & 1) * 64 * LDH;

        // ---- prefetch tile j+1 into the other stage ------------------------
        if (j + 1 < nkt) {
            const uint32_t kn = KHI_OFF + (uint32_t)((j + 1) & 1) * 64 * LDH;
            const uint32_t vn = VHI_OFF + (uint32_t)((j + 1) & 1) * 64 * LDH;
            #pragma unroll
            for (int i = 0; i < 16; i++) {
                int idx = tid + i * 128;
                int row = idx >> 5, c4 = idx & 31;
                size_t goff = base + (size_t)(64 * (j + 1) + row) * DH + 4 * c4;
                float4 kv = *(const float4*)(Kg + goff);
                float4 vv = *(const float4*)(Vg + goff);
                uint32_t p = row * LDH + 4 * c4;
                *(uint32_t*)&sm[kn + p]     = packh2(__float2half_rn(kv.x), __float2half_rn(kv.y));
                *(uint32_t*)&sm[kn + p + 2] = packh2(__float2half_rn(kv.z), __float2half_rn(kv.w));
                *(uint32_t*)&sm[vn + p]     = packh2(__float2half_rn(vv.x), __float2half_rn(vv.y));
                *(uint32_t*)&sm[vn + p + 2] = packh2(__float2half_rn(vv.z), __float2half_rn(vv.w));
            }
        }

        // ---- S = Q K^T  (2-pass: Qhi*K + Qlo*K), log2-domain scores --------
        float S_[8][4];
        #pragma unroll
        for (int n = 0; n < 8; n++)
            #pragma unroll
            for (int e = 0; e < 4; e++) S_[n][e] = 0.0f;

        #pragma unroll
        for (int s = 0; s < 8; s++) {
            uint32_t qh[4], ql[4];
            uint32_t qa = sb + 2u * (uint32_t)(a_row * LDH + 16 * s + a_col8);
            ldsm4(qh, qa + 2u * QHI_OFF);
            ldsm4(ql, qa + 2u * QLO_OFF);
            #pragma unroll
            for (int t = 0; t < 4; t++) {
                uint32_t bhh[4];
                uint32_t ka = sb + 2u * (uint32_t)(kbuf + (16 * t + bk_rowi) * LDH
                                                   + 16 * s + bk_col8);
                ldsm4(bhh, ka);
                mma16816(S_[2 * t],     qh, bhh);
                mma16816(S_[2 * t + 1], qh, bhh + 2);
                mma16816(S_[2 * t],     ql, bhh);
                mma16816(S_[2 * t + 1], ql, bhh + 2);
            }
        }

        // ---- causal mask (diagonal tile only) ------------------------------
        const int rowA = qr0 + 16 * w + g;
        const int rowB = rowA + 8;
        if (j == qt) {
            int kb = 64 * j;
            #pragma unroll
            for (int n = 0; n < 8; n++) {
                #pragma unroll
                for (int e = 0; e < 2; e++) {
                    int key = kb + 8 * n + 2 * c + e;
                    if (key > rowA) S_[n][e]     = -1e30f;
                    if (key > rowB) S_[n][2 + e] = -1e30f;
                }
            }
        }

        // ---- online softmax (quad-local rows, exp2 domain) -----------------
        float mtA = -1e30f, mtB = -1e30f;
        #pragma unroll
        for (int n = 0; n < 8; n++) {
            mtA = fmaxf(mtA, fmaxf(S_[n][0], S_[n][1]));
            mtB = fmaxf(mtB, fmaxf(S_[n][2], S_[n][3]));
        }
        mtA = fmaxf(mtA, __shfl_xor_sync(0xffffffffu, mtA, 1));
        mtA = fmaxf(mtA, __shfl_xor_sync(0xffffffffu, mtA, 2));
        mtB = fmaxf(mtB, __shfl_xor_sync(0xffffffffu, mtB, 1));
        mtB = fmaxf(mtB, __shfl_xor_sync(0xffffffffu, mtB, 2));

        float mnA = fmaxf(mA, mtA), mnB = fmaxf(mB, mtB);
        float corrA = ex2f(mA - mnA), corrB = ex2f(mB - mnB);

        float sA = 0.0f, sB = 0.0f;
        #pragma unroll
        for (int n = 0; n < 8; n++) {
            S_[n][0] = ex2f(S_[n][0] - mnA);
            S_[n][1] = ex2f(S_[n][1] - mnA);
            S_[n][2] = ex2f(S_[n][2] - mnB);
            S_[n][3] = ex2f(S_[n][3] - mnB);
            sA += S_[n][0] + S_[n][1];
            sB += S_[n][2] + S_[n][3];
        }
        sA += __shfl_xor_sync(0xffffffffu, sA, 1);
        sA += __shfl_xor_sync(0xffffffffu, sA, 2);
        sB += __shfl_xor_sync(0xffffffffu, sB, 1);
        sB += __shfl_xor_sync(0xffffffffu, sB, 2);

        lA = lA * corrA + sA;  mA = mnA;
        lB = lB * corrB + sB;  mB = mnB;

        #pragma unroll
        for (int n = 0; n < 16; n++) {
            O_[n][0] *= corrA; O_[n][1] *= corrA;
            O_[n][2] *= corrB; O_[n][3] *= corrB;
        }

        // ---- P: C-layout -> fp16 A-fragments (hi only) ---------------------
        uint32_t ph[4][4];
        #pragma unroll
        for (int s = 0; s < 4; s++) {
            #pragma unroll
            for (int half_ : {0, 1}) {
                const float* src = S_[2 * s + half_];
                ph[s][2 * half_]     = packh2(__float2half_rn(src[0]),
                                              __float2half_rn(src[1]));
                ph[s][2 * half_ + 1] = packh2(__float2half_rn(src[2]),
                                              __float2half_rn(src[3]));
            }
        }

        // ---- O += P V  (single pass) ---------------------------------------
        #pragma unroll
        for (int s = 0; s < 4; s++) {
            #pragma unroll
            for (int t = 0; t < 8; t++) {
                uint32_t vh[4];
                uint32_t va = sb + 2u * (uint32_t)(vbuf + (16 * s + bv_rowi) * LDH
                                                   + 16 * t + bv_col8);
                ldsm4t(vh, va);
                mma16816(O_[2 * t],     ph[s], vh);
                mma16816(O_[2 * t + 1], ph[s], vh + 2);
            }
        }

        __syncthreads();   // publish prefetched tile j+1; free buffer j
    }

    // ---- epilogue: O /= l, store fp32 -------------------------------------
    {
        float iA = 1.0f / lA, iB = 1.0f / lB;
        const int rowA = qr0 + 16 * w + g;
        float* oA = Og + base + (size_t)rowA * DH;
        float* oB = oA + 8 * DH;
        #pragma unroll
        for (int n = 0; n < 16; n++) {
            *(float2*)(oA + 8 * n + 2 * c) =
                make_float2(O_[n][0] * iA, O_[n][1] * iA);
            *(float2*)(oB + 8 * n + 2 * c) =
                make_float2(O_[n][2] * iB, O_[n][3] * iB);
        }
    }
}

// ---------------------------------------------------------------------------
extern "C" void kernel_launch(void* const* d_in, const int* in_sizes, int n_in,
                              void* d_out, int out_size) {
    const float* Q = (const float*)d_in[0];
    const float* K = (const float*)d_in[1];
    const float* V = (const float*)d_in[2];
    // d_in[3] = causal mask (known tril) — applied analytically in-kernel.
    float* O = (float*)d_out;

    cudaFuncSetAttribute(fa2_hmma_kernel,
                         cudaFuncAttributeMaxDynamicSharedMemorySize, SMEM_BYTES);

    dim3 grid(64, 32, 1);   // bh x 64-row q-tiles (heavy first)
    fa2_hmma_kernel<<<grid, 128, SMEM_BYTES>>>(Q, K, V, O);
}

// round 6
// speedup vs baseline: 1.0989x; 1.0989x over previous
#include <cuda_runtime.h>
#include <cuda_fp16.h>
#include <cstdint>

// ============================================================================
// ScaledDotProductAttention  B=4 H=16 S=2048 D=128, causal, fp32 in/out
// FlashAttention-2, mma.sync.m16n8k16 HMMA.
// R6 = R4 structure (128-query CTA / 256 thr / double-buffered 64-key tiles)
//      + single-pass PV (validated in R5: rel_err 3.2e-4)
//      + exp2-domain softmax (Q pre-scaled by scale*log2e).
// R5's 64-row-CTA experiment regressed (regs 254, per-iter overhead doubled);
// M=128 per CTA is the efficiency sweet spot.
// ============================================================================

static constexpr int SEQ = 2048;
static constexpr int DH  = 128;
static constexpr float SCALE_LOG2E = 0.08838834764831845f * 1.4426950408889634f;

static constexpr int LDH = 136;   // padded SMEM stride in halfs

// SMEM layout (half units)
enum : uint32_t {
    QHI_OFF = 0,
    QLO_OFF = QHI_OFF + 128 * LDH,
    KHI_OFF = QLO_OFF + 128 * LDH,     // 2 stages x 64 rows
    VHI_OFF = KHI_OFF + 2 * 64 * LDH,  // 2 stages x 64 rows
    SMEM_HALVES = VHI_OFF + 2 * 64 * LDH
};
static constexpr uint32_t SMEM_BYTES = SMEM_HALVES * 2;   // 139264

// ---------------------------------------------------------------------------
__device__ __forceinline__ uint32_t cvta_s(const void* p) {
    uint32_t a;
    asm("{ .reg .u64 t; cvta.to.shared.u64 t, %1; cvt.u32.u64 %0, t; }"
        : "=r"(a) : "l"(p));
    return a;
}

__device__ __forceinline__ float ex2f(float x) {
    float r;
    asm("ex2.approx.f32 %0, %1;" : "=f"(r) : "f"(x));
    return r;
}

__device__ __forceinline__ void ldsm4(uint32_t r[4], uint32_t addr) {
    asm volatile("ldmatrix.sync.aligned.m8n8.x4.shared.b16 {%0,%1,%2,%3}, [%4];"
                 : "=r"(r[0]), "=r"(r[1]), "=r"(r[2]), "=r"(r[3]) : "r"(addr));
}

__device__ __forceinline__ void ldsm4t(uint32_t r[4], uint32_t addr) {
    asm volatile("ldmatrix.sync.aligned.m8n8.x4.trans.shared.b16 {%0,%1,%2,%3}, [%4];"
                 : "=r"(r[0]), "=r"(r[1]), "=r"(r[2]), "=r"(r[3]) : "r"(addr));
}

__device__ __forceinline__ void mma16816(float d[4], const uint32_t a[4],
                                         const uint32_t b[2]) {
    asm volatile(
        "mma.sync.aligned.m16n8k16.row.col.f32.f16.f16.f32 "
        "{%0,%1,%2,%3}, {%4,%5,%6,%7}, {%8,%9}, {%0,%1,%2,%3};"
        : "+f"(d[0]), "+f"(d[1]), "+f"(d[2]), "+f"(d[3])
        : "r"(a[0]), "r"(a[1]), "r"(a[2]), "r"(a[3]), "r"(b[0]), "r"(b[1]));
}

__device__ __forceinline__ uint32_t packh2(__half a, __half b) {
    return (uint32_t)__half_as_ushort(a) | ((uint32_t)__half_as_ushort(b) << 16);
}

// ---------------------------------------------------------------------------
__global__ void __launch_bounds__(256, 1)
fa2_hmma_kernel(const float* __restrict__ Qg, const float* __restrict__ Kg,
                const float* __restrict__ Vg, float* __restrict__ Og)
{
    extern __shared__ __half sm[];
    const uint32_t sb = cvta_s(sm);
    const int tid  = threadIdx.x;
    const int w    = tid >> 5;
    const int lane = tid & 31;
    const int g    = lane >> 2;    // row group 0..7
    const int c    = lane & 3;     // col pair 0..3
    const int bh   = blockIdx.x;
    const int qt   = 15 - (int)blockIdx.y;        // heavy q-tiles first
    const size_t base = (size_t)bh * SEQ * DH;
    const int qr0  = qt * 128;

    // ldmatrix per-lane address components
    const int a_row  = 16 * w + (lane & 7) + ((lane >> 3) & 1) * 8;
    const int a_col8 = (lane >> 4) * 8;
    const int bk_rowi = (lane & 7) + (lane >> 4) * 8;
    const int bk_col8 = ((lane >> 3) & 1) * 8;
    const int bv_rowi = (lane & 7) + ((lane >> 3) & 1) * 8;
    const int bv_col8 = (lane >> 4) * 8;

    // per-thread K/V load coordinates
    const int ld_row = tid >> 5;          // 0..7 base row, step 8
    const int ld_c4  = tid & 31;          // float4 index within 128-d row

    // ---- prologue: Q tile -> split fp16 SMEM (pre-scaled by scale*log2e) ---
    #pragma unroll
    for (int i = 0; i < 16; i++) {
        int idx = tid + i * 256;
        int row = idx >> 5, c4 = idx & 31;
        float4 v = *(const float4*)(Qg + base + (size_t)(qr0 + row) * DH + 4 * c4);
        v.x *= SCALE_LOG2E; v.y *= SCALE_LOG2E;
        v.z *= SCALE_LOG2E; v.w *= SCALE_LOG2E;
        __half hx = __float2half_rn(v.x), hy = __float2half_rn(v.y);
        __half hz = __float2half_rn(v.z), hw = __float2half_rn(v.w);
        uint32_t p = row * LDH + 4 * c4;
        *(uint32_t*)&sm[QHI_OFF + p]     = packh2(hx, hy);
        *(uint32_t*)&sm[QHI_OFF + p + 2] = packh2(hz, hw);
        *(uint32_t*)&sm[QLO_OFF + p] =
            packh2(__float2half_rn(v.x - __half2float(hx)),
                   __float2half_rn(v.y - __half2float(hy)));
        *(uint32_t*)&sm[QLO_OFF + p + 2] =
            packh2(__float2half_rn(v.z - __half2float(hz)),
                   __float2half_rn(v.w - __half2float(hw)));
    }

    const int nkt = 2 * (qt + 1);

    // ---- preload K/V tile 0 into stage 0 -----------------------------------
    #pragma unroll
    for (int i = 0; i < 8; i++) {
        int row = ld_row + 8 * i;
        size_t goff = base + (size_t)row * DH + 4 * ld_c4;
        float4 kv = *(const float4*)(Kg + goff);
        float4 vv = *(const float4*)(Vg + goff);
        uint32_t p = row * LDH + 4 * ld_c4;
        *(uint32_t*)&sm[KHI_OFF + p]     = packh2(__float2half_rn(kv.x), __float2half_rn(kv.y));
        *(uint32_t*)&sm[KHI_OFF + p + 2] = packh2(__float2half_rn(kv.z), __float2half_rn(kv.w));
        *(uint32_t*)&sm[VHI_OFF + p]     = packh2(__float2half_rn(vv.x), __float2half_rn(vv.y));
        *(uint32_t*)&sm[VHI_OFF + p + 2] = packh2(__float2half_rn(vv.z), __float2half_rn(vv.w));
    }

    float O_[16][4];
    #pragma unroll
    for (int n = 0; n < 16; n++)
        #pragma unroll
        for (int e = 0; e < 4; e++) O_[n][e] = 0.0f;
    float mA = -1e30f, mB = -1e30f, lA = 0.0f, lB = 0.0f;

    __syncthreads();

    for (int j = 0; j < nkt; j++) {
        const uint32_t kbuf = KHI_OFF + (uint32_t)(j & 1) * 64 * LDH;
        const uint32_t vbuf = VHI_OFF + (uint32_t)(j & 1) * 64 * LDH;

        // ---- prefetch tile j+1 into the other stage ------------------------
        if (j + 1 < nkt) {
            const uint32_t kn = KHI_OFF + (uint32_t)((j + 1) & 1) * 64 * LDH;
            const uint32_t vn = VHI_OFF + (uint32_t)((j + 1) & 1) * 64 * LDH;
            #pragma unroll
            for (int i = 0; i < 8; i++) {
                int row = ld_row + 8 * i;
                size_t goff = base + (size_t)(64 * (j + 1) + row) * DH + 4 * ld_c4;
                float4 kv = *(const float4*)(Kg + goff);
                float4 vv = *(const float4*)(Vg + goff);
                uint32_t p = row * LDH + 4 * ld_c4;
                *(uint32_t*)&sm[kn + p]     = packh2(__float2half_rn(kv.x), __float2half_rn(kv.y));
                *(uint32_t*)&sm[kn + p + 2] = packh2(__float2half_rn(kv.z), __float2half_rn(kv.w));
                *(uint32_t*)&sm[vn + p]     = packh2(__float2half_rn(vv.x), __float2half_rn(vv.y));
                *(uint32_t*)&sm[vn + p + 2] = packh2(__float2half_rn(vv.z), __float2half_rn(vv.w));
            }
        }

        // ---- S = Q K^T  (2-pass: Qhi*K + Qlo*K), log2-domain scores --------
        float S_[8][4];
        #pragma unroll
        for (int n = 0; n < 8; n++)
            #pragma unroll
            for (int e = 0; e < 4; e++) S_[n][e] = 0.0f;

        #pragma unroll
        for (int s = 0; s < 8; s++) {
            uint32_t qh[4], ql[4];
            uint32_t qa = sb + 2u * (uint32_t)(a_row * LDH + 16 * s + a_col8);
            ldsm4(qh, qa + 2u * QHI_OFF);
            ldsm4(ql, qa + 2u * QLO_OFF);
            #pragma unroll
            for (int t = 0; t < 4; t++) {
                uint32_t bhh[4];
                uint32_t ka = sb + 2u * (uint32_t)(kbuf + (16 * t + bk_rowi) * LDH
                                                   + 16 * s + bk_col8);
                ldsm4(bhh, ka);
                mma16816(S_[2 * t],     qh, bhh);
                mma16816(S_[2 * t + 1], qh, bhh + 2);
                mma16816(S_[2 * t],     ql, bhh);
                mma16816(S_[2 * t + 1], ql, bhh + 2);
            }
        }

        // ---- causal mask (diagonal-overlap tiles only) ---------------------
        const int rowA = qr0 + 16 * w + g;
        const int rowB = rowA + 8;
        if (j >= 2 * qt) {
            int kb = 64 * j;
            #pragma unroll
            for (int n = 0; n < 8; n++) {
                #pragma unroll
                for (int e = 0; e < 2; e++) {
                    int key = kb + 8 * n + 2 * c + e;
                    if (key > rowA) S_[n][e]     = -1e30f;
                    if (key > rowB) S_[n][2 + e] = -1e30f;
                }
            }
        }

        // ---- online softmax (quad-local rows, exp2 domain) -----------------
        float mtA = -1e30f, mtB = -1e30f;
        #pragma unroll
        for (int n = 0; n < 8; n++) {
            mtA = fmaxf(mtA, fmaxf(S_[n][0], S_[n][1]));
            mtB = fmaxf(mtB, fmaxf(S_[n][2], S_[n][3]));
        }
        mtA = fmaxf(mtA, __shfl_xor_sync(0xffffffffu, mtA, 1));
        mtA = fmaxf(mtA, __shfl_xor_sync(0xffffffffu, mtA, 2));
        mtB = fmaxf(mtB, __shfl_xor_sync(0xffffffffu, mtB, 1));
        mtB = fmaxf(mtB, __shfl_xor_sync(0xffffffffu, mtB, 2));

        float mnA = fmaxf(mA, mtA), mnB = fmaxf(mB, mtB);
        float corrA = ex2f(mA - mnA), corrB = ex2f(mB - mnB);

        float sA = 0.0f, sB = 0.0f;
        #pragma unroll
        for (int n = 0; n < 8; n++) {
            S_[n][0] = ex2f(S_[n][0] - mnA);
            S_[n][1] = ex2f(S_[n][1] - mnA);
            S_[n][2] = ex2f(S_[n][2] - mnB);
            S_[n][3] = ex2f(S_[n][3] - mnB);
            sA += S_[n][0] + S_[n][1];
            sB += S_[n][2] + S_[n][3];
        }
        sA += __shfl_xor_sync(0xffffffffu, sA, 1);
        sA += __shfl_xor_sync(0xffffffffu, sA, 2);
        sB += __shfl_xor_sync(0xffffffffu, sB, 1);
        sB += __shfl_xor_sync(0xffffffffu, sB, 2);

        lA = lA * corrA + sA;  mA = mnA;
        lB = lB * corrB + sB;  mB = mnB;

        #pragma unroll
        for (int n = 0; n < 16; n++) {
            O_[n][0] *= corrA; O_[n][1] *= corrA;
            O_[n][2] *= corrB; O_[n][3] *= corrB;
        }

        // ---- P: C-layout -> fp16 A-fragments (hi only, single-pass PV) -----
        uint32_t ph[4][4];
        #pragma unroll
        for (int s = 0; s < 4; s++) {
            #pragma unroll
            for (int half_ : {0, 1}) {
                const float* src = S_[2 * s + half_];
                ph[s][2 * half_]     = packh2(__float2half_rn(src[0]),
                                              __float2half_rn(src[1]));
                ph[s][2 * half_ + 1] = packh2(__float2half_rn(src[2]),
                                              __float2half_rn(src[3]));
            }
        }

        // ---- O += P V  (single pass) ---------------------------------------
        #pragma unroll
        for (int s = 0; s < 4; s++) {
            #pragma unroll
            for (int t = 0; t < 8; t++) {
                uint32_t vh[4];
                uint32_t va = sb + 2u * (uint32_t)(vbuf + (16 * s + bv_rowi) * LDH
                                                   + 16 * t + bv_col8);
                ldsm4t(vh, va);
                mma16816(O_[2 * t],     ph[s], vh);
                mma16816(O_[2 * t + 1], ph[s], vh + 2);
            }
        }

        __syncthreads();   // publish prefetched tile j+1; free buffer j
    }

    // ---- epilogue: O /= l, store fp32 -------------------------------------
    {
        float iA = 1.0f / lA, iB = 1.0f / lB;
        const int rowA = qr0 + 16 * w + g;
        float* oA = Og + base + (size_t)rowA * DH;
        float* oB = oA + 8 * DH;
        #pragma unroll
        for (int n = 0; n < 16; n++) {
            *(float2*)(oA + 8 * n + 2 * c) =
                make_float2(O_[n][0] * iA, O_[n][1] * iA);
            *(float2*)(oB + 8 * n + 2 * c) =
                make_float2(O_[n][2] * iB, O_[n][3] * iB);
        }
    }
}

// ---------------------------------------------------------------------------
extern "C" void kernel_launch(void* const* d_in, const int* in_sizes, int n_in,
                              void* d_out, int out_size) {
    const float* Q = (const float*)d_in[0];
    const float* K = (const float*)d_in[1];
    const float* V = (const float*)d_in[2];
    // d_in[3] = causal mask (known tril) — applied analytically in-kernel.
    float* O = (float*)d_out;

    cudaFuncSetAttribute(fa2_hmma_kernel,
                         cudaFuncAttributeMaxDynamicSharedMemorySize, SMEM_BYTES);

    dim3 grid(64, 16, 1);
    fa2_hmma_kernel<<<grid, 256, SMEM_BYTES>>>(Q, K, V, O);
}

// round 7
// speedup vs baseline: 1.2433x; 1.1314x over previous
#include <cuda_runtime.h>
#include <cuda_fp16.h>
#include <cstdint>

// ============================================================================
// ScaledDotProductAttention  B=4 H=16 S=2048 D=128, causal, fp32 in/out
// FlashAttention-2, mma.sync.m16n8k16 HMMA.
// R7 = R6 (128-q CTA / 256 thr / double-buffered 64-key tiles, exp2 softmax,
//      single-pass PV) with:
//   * Q single fp16 (Q-lo pass dropped). Calibrated error budget:
//     K+V=2.8e-4, +P-hi=3.2e-4, +Q-hi ~= 4.3e-4 total (gate 1e-3).
//     MMAs/iter 192 -> 128; S-chains halve; smem 139 -> 104 KB.
//   * l kept thread-partial; quad reduction deferred to epilogue
//     (saves 4 shfl per iteration).
// Kernel is latency-bound (R6: issue 25.3%, tensor 42.9%, regs 241 = RF-full)
// so the lever is critical-path length, not pipe throughput.
// ============================================================================

static constexpr int SEQ = 2048;
static constexpr int DH  = 128;
static constexpr float SCALE_LOG2E = 0.08838834764831845f * 1.4426950408889634f;

static constexpr int LDH = 136;   // padded SMEM stride in halfs

// SMEM layout (half units)
enum : uint32_t {
    Q_OFF   = 0,
    KHI_OFF = Q_OFF + 128 * LDH,       // 2 stages x 64 rows
    VHI_OFF = KHI_OFF + 2 * 64 * LDH,  // 2 stages x 64 rows
    SMEM_HALVES = VHI_OFF + 2 * 64 * LDH
};
static constexpr uint32_t SMEM_BYTES = SMEM_HALVES * 2;   // 104448

// ---------------------------------------------------------------------------
__device__ __forceinline__ uint32_t cvta_s(const void* p) {
    uint32_t a;
    asm("{ .reg .u64 t; cvta.to.shared.u64 t, %1; cvt.u32.u64 %0, t; }"
        : "=r"(a) : "l"(p));
    return a;
}

__device__ __forceinline__ float ex2f(float x) {
    float r;
    asm("ex2.approx.f32 %0, %1;" : "=f"(r) : "f"(x));
    return r;
}

__device__ __forceinline__ void ldsm4(uint32_t r[4], uint32_t addr) {
    asm volatile("ldmatrix.sync.aligned.m8n8.x4.shared.b16 {%0,%1,%2,%3}, [%4];"
                 : "=r"(r[0]), "=r"(r[1]), "=r"(r[2]), "=r"(r[3]) : "r"(addr));
}

__device__ __forceinline__ void ldsm4t(uint32_t r[4], uint32_t addr) {
    asm volatile("ldmatrix.sync.aligned.m8n8.x4.trans.shared.b16 {%0,%1,%2,%3}, [%4];"
                 : "=r"(r[0]), "=r"(r[1]), "=r"(r[2]), "=r"(r[3]) : "r"(addr));
}

__device__ __forceinline__ void mma16816(float d[4], const uint32_t a[4],
                                         const uint32_t b[2]) {
    asm volatile(
        "mma.sync.aligned.m16n8k16.row.col.f32.f16.f16.f32 "
        "{%0,%1,%2,%3}, {%4,%5,%6,%7}, {%8,%9}, {%0,%1,%2,%3};"
        : "+f"(d[0]), "+f"(d[1]), "+f"(d[2]), "+f"(d[3])
        : "r"(a[0]), "r"(a[1]), "r"(a[2]), "r"(a[3]), "r"(b[0]), "r"(b[1]));
}

__device__ __forceinline__ uint32_t packh2(__half a, __half b) {
    return (uint32_t)__half_as_ushort(a) | ((uint32_t)__half_as_ushort(b) << 16);
}

// ---------------------------------------------------------------------------
__global__ void __launch_bounds__(256, 1)
fa2_hmma_kernel(const float* __restrict__ Qg, const float* __restrict__ Kg,
                const float* __restrict__ Vg, float* __restrict__ Og)
{
    extern __shared__ __half sm[];
    const uint32_t sb = cvta_s(sm);
    const int tid  = threadIdx.x;
    const int w    = tid >> 5;
    const int lane = tid & 31;
    const int g    = lane >> 2;    // row group 0..7
    const int c    = lane & 3;     // col pair 0..3
    const int bh   = blockIdx.x;
    const int qt   = 15 - (int)blockIdx.y;        // heavy q-tiles first
    const size_t base = (size_t)bh * SEQ * DH;
    const int qr0  = qt * 128;

    // ldmatrix per-lane address components
    const int a_row  = 16 * w + (lane & 7) + ((lane >> 3) & 1) * 8;
    const int a_col8 = (lane >> 4) * 8;
    const int bk_rowi = (lane & 7) + (lane >> 4) * 8;
    const int bk_col8 = ((lane >> 3) & 1) * 8;
    const int bv_rowi = (lane & 7) + ((lane >> 3) & 1) * 8;
    const int bv_col8 = (lane >> 4) * 8;

    // per-thread K/V load coordinates
    const int ld_row = tid >> 5;          // 0..7 base row, step 8
    const int ld_c4  = tid & 31;          // float4 index within 128-d row

    // ---- prologue: Q tile -> fp16 SMEM (pre-scaled by scale*log2e) ---------
    #pragma unroll
    for (int i = 0; i < 16; i++) {
        int idx = tid + i * 256;
        int row = idx >> 5, c4 = idx & 31;
        float4 v = *(const float4*)(Qg + base + (size_t)(qr0 + row) * DH + 4 * c4);
        v.x *= SCALE_LOG2E; v.y *= SCALE_LOG2E;
        v.z *= SCALE_LOG2E; v.w *= SCALE_LOG2E;
        uint32_t p = row * LDH + 4 * c4;
        *(uint32_t*)&sm[Q_OFF + p]     = packh2(__float2half_rn(v.x), __float2half_rn(v.y));
        *(uint32_t*)&sm[Q_OFF + p + 2] = packh2(__float2half_rn(v.z), __float2half_rn(v.w));
    }

    const int nkt = 2 * (qt + 1);

    // ---- preload K/V tile 0 into stage 0 -----------------------------------
    #pragma unroll
    for (int i = 0; i < 8; i++) {
        int row = ld_row + 8 * i;
        size_t goff = base + (size_t)row * DH + 4 * ld_c4;
        float4 kv = *(const float4*)(Kg + goff);
        float4 vv = *(const float4*)(Vg + goff);
        uint32_t p = row * LDH + 4 * ld_c4;
        *(uint32_t*)&sm[KHI_OFF + p]     = packh2(__float2half_rn(kv.x), __float2half_rn(kv.y));
        *(uint32_t*)&sm[KHI_OFF + p + 2] = packh2(__float2half_rn(kv.z), __float2half_rn(kv.w));
        *(uint32_t*)&sm[VHI_OFF + p]     = packh2(__float2half_rn(vv.x), __float2half_rn(vv.y));
        *(uint32_t*)&sm[VHI_OFF + p + 2] = packh2(__float2half_rn(vv.z), __float2half_rn(vv.w));
    }

    float O_[16][4];
    #pragma unroll
    for (int n = 0; n < 16; n++)
        #pragma unroll
        for (int e = 0; e < 4; e++) O_[n][e] = 0.0f;
    float mA = -1e30f, mB = -1e30f, lA = 0.0f, lB = 0.0f;  // l: thread-partial

    __syncthreads();

    for (int j = 0; j < nkt; j++) {
        const uint32_t kbuf = KHI_OFF + (uint32_t)(j & 1) * 64 * LDH;
        const uint32_t vbuf = VHI_OFF + (uint32_t)(j & 1) * 64 * LDH;

        // ---- prefetch tile j+1 into the other stage ------------------------
        if (j + 1 < nkt) {
            const uint32_t kn = KHI_OFF + (uint32_t)((j + 1) & 1) * 64 * LDH;
            const uint32_t vn = VHI_OFF + (uint32_t)((j + 1) & 1) * 64 * LDH;
            #pragma unroll
            for (int i = 0; i < 8; i++) {
                int row = ld_row + 8 * i;
                size_t goff = base + (size_t)(64 * (j + 1) + row) * DH + 4 * ld_c4;
                float4 kv = *(const float4*)(Kg + goff);
                float4 vv = *(const float4*)(Vg + goff);
                uint32_t p = row * LDH + 4 * ld_c4;
                *(uint32_t*)&sm[kn + p]     = packh2(__float2half_rn(kv.x), __float2half_rn(kv.y));
                *(uint32_t*)&sm[kn + p + 2] = packh2(__float2half_rn(kv.z), __float2half_rn(kv.w));
                *(uint32_t*)&sm[vn + p]     = packh2(__float2half_rn(vv.x), __float2half_rn(vv.y));
                *(uint32_t*)&sm[vn + p + 2] = packh2(__float2half_rn(vv.z), __float2half_rn(vv.w));
            }
        }

        // ---- S = Q K^T  (single pass, log2-domain scores) ------------------
        float S_[8][4];
        #pragma unroll
        for (int n = 0; n < 8; n++)
            #pragma unroll
            for (int e = 0; e < 4; e++) S_[n][e] = 0.0f;

        #pragma unroll
        for (int s = 0; s < 8; s++) {
            uint32_t qh[4];
            uint32_t qa = sb + 2u * (uint32_t)(Q_OFF + a_row * LDH + 16 * s + a_col8);
            ldsm4(qh, qa);
            #pragma unroll
            for (int t = 0; t < 4; t++) {
                uint32_t bhh[4];
                uint32_t ka = sb + 2u * (uint32_t)(kbuf + (16 * t + bk_rowi) * LDH
                                                   + 16 * s + bk_col8);
                ldsm4(bhh, ka);
                mma16816(S_[2 * t],     qh, bhh);
                mma16816(S_[2 * t + 1], qh, bhh + 2);
            }
        }

        // ---- causal mask (diagonal-overlap tiles only) ---------------------
        const int rowA = qr0 + 16 * w + g;
        const int rowB = rowA + 8;
        if (j >= 2 * qt) {
            int kb = 64 * j;
            #pragma unroll
            for (int n = 0; n < 8; n++) {
                #pragma unroll
                for (int e = 0; e < 2; e++) {
                    int key = kb + 8 * n + 2 * c + e;
                    if (key > rowA) S_[n][e]     = -1e30f;
                    if (key > rowB) S_[n][2 + e] = -1e30f;
                }
            }
        }

        // ---- online softmax (quad-local max; l thread-partial) -------------
        float mtA = -1e30f, mtB = -1e30f;
        #pragma unroll
        for (int n = 0; n < 8; n++) {
            mtA = fmaxf(mtA, fmaxf(S_[n][0], S_[n][1]));
            mtB = fmaxf(mtB, fmaxf(S_[n][2], S_[n][3]));
        }
        mtA = fmaxf(mtA, __shfl_xor_sync(0xffffffffu, mtA, 1));
        mtA = fmaxf(mtA, __shfl_xor_sync(0xffffffffu, mtA, 2));
        mtB = fmaxf(mtB, __shfl_xor_sync(0xffffffffu, mtB, 1));
        mtB = fmaxf(mtB, __shfl_xor_sync(0xffffffffu, mtB, 2));

        float mnA = fmaxf(mA, mtA), mnB = fmaxf(mB, mtB);
        float corrA = ex2f(mA - mnA), corrB = ex2f(mB - mnB);

        float sA = 0.0f, sB = 0.0f;
        #pragma unroll
        for (int n = 0; n < 8; n++) {
            S_[n][0] = ex2f(S_[n][0] - mnA);
            S_[n][1] = ex2f(S_[n][1] - mnA);
            S_[n][2] = ex2f(S_[n][2] - mnB);
            S_[n][3] = ex2f(S_[n][3] - mnB);
            sA += S_[n][0] + S_[n][1];
            sB += S_[n][2] + S_[n][3];
        }
        lA = lA * corrA + sA;  mA = mnA;   // thread-partial l
        lB = lB * corrB + sB;  mB = mnB;

        #pragma unroll
        for (int n = 0; n < 16; n++) {
            O_[n][0] *= corrA; O_[n][1] *= corrA;
            O_[n][2] *= corrB; O_[n][3] *= corrB;
        }

        // ---- P: C-layout -> fp16 A-fragments -------------------------------
        uint32_t ph[4][4];
        #pragma unroll
        for (int s = 0; s < 4; s++) {
            #pragma unroll
            for (int half_ : {0, 1}) {
                const float* src = S_[2 * s + half_];
                ph[s][2 * half_]     = packh2(__float2half_rn(src[0]),
                                              __float2half_rn(src[1]));
                ph[s][2 * half_ + 1] = packh2(__float2half_rn(src[2]),
                                              __float2half_rn(src[3]));
            }
        }

        // ---- O += P V  (single pass) ---------------------------------------
        #pragma unroll
        for (int s = 0; s < 4; s++) {
            #pragma unroll
            for (int t = 0; t < 8; t++) {
                uint32_t vh[4];
                uint32_t va = sb + 2u * (uint32_t)(vbuf + (16 * s + bv_rowi) * LDH
                                                   + 16 * t + bv_col8);
                ldsm4t(vh, va);
                mma16816(O_[2 * t],     ph[s], vh);
                mma16816(O_[2 * t + 1], ph[s], vh + 2);
            }
        }

        __syncthreads();   // publish prefetched tile j+1; free buffer j
    }

    // ---- epilogue: reduce l across quad, O /= l, store fp32 ----------------
    {
        lA += __shfl_xor_sync(0xffffffffu, lA, 1);
        lA += __shfl_xor_sync(0xffffffffu, lA, 2);
        lB += __shfl_xor_sync(0xffffffffu, lB, 1);
        lB += __shfl_xor_sync(0xffffffffu, lB, 2);
        float iA = 1.0f / lA, iB = 1.0f / lB;
        const int rowA = qr0 + 16 * w + g;
        float* oA = Og + base + (size_t)rowA * DH;
        float* oB = oA + 8 * DH;
        #pragma unroll
        for (int n = 0; n < 16; n++) {
            *(float2*)(oA + 8 * n + 2 * c) =
                make_float2(O_[n][0] * iA, O_[n][1] * iA);
            *(float2*)(oB + 8 * n + 2 * c) =
                make_float2(O_[n][2] * iB, O_[n][3] * iB);
        }
    }
}

// ---------------------------------------------------------------------------
extern "C" void kernel_launch(void* const* d_in, const int* in_sizes, int n_in,
                              void* d_out, int out_size) {
    const float* Q = (const float*)d_in[0];
    const float* K = (const float*)d_in[1];
    const float* V = (const float*)d_in[2];
    // d_in[3] = causal mask (known tril) — applied analytically in-kernel.
    float* O = (float*)d_out;

    cudaFuncSetAttribute(fa2_hmma_kernel,
                         cudaFuncAttributeMaxDynamicSharedMemorySize, SMEM_BYTES);

    dim3 grid(64, 16, 1);
    fa2_hmma_kernel<<<grid, 256, SMEM_BYTES>>>(Q, K, V, O);
}